// round 8
// baseline (speedup 1.0000x reference)
#include <cuda_runtime.h>

// Problem constants
#define B_IMG 8
#define H_IMG 1024
#define W_IMG 1024
#define HW (H_IMG * W_IMG)

#define TILE   32          // output tile per block (32x32 pixels)
#define YHALO  7           // search radius 5 + patch radius 2
#define RHALO  5           // search radius for rgb gather
#define YH     (TILE + 2*YHALO)   // 46
#define YS     (YH + 2)           // 48 stride
#define DH     (TILE + 4)         // 36 : tile + patch halo (2 each side)
#define DS     (DH + 4)           // 40 stride (even -> float2-aligned at even cols)
#define RH     (TILE + 2*RHALO)   // 42
#define NT     512                // threads per block (16 warps)

// Dynamic smem layout (float offsets)
#define SY_OFF   0                    // 46*48 = 2208
#define SD_OFF   2208                 // 2 x (36*40 = 1440)
#define SHS_OFF  (2208 + 2*1440)     // 5088 : 2 x (36*32 = 1152)
#define SR_OFF   (5088 + 2*1152)     // 7392 : 3 x (42*42 = 1764)
#define SMEM_FLOATS (7392 + 3*1764)  // 12684
#define SMEM_BYTES  (SMEM_FLOATS * 4) // 50736

// Scratch: luminance plane (8 * 1M floats = 32 MiB) — static device array,
// allowed under the allocation guards.
__device__ float g_y[B_IMG * HW];

// ---------------------------------------------------------------------------
// Kernel 1: y = mean(rgb, channel) — vectorized float4
// ---------------------------------------------------------------------------
__global__ void lum_kernel(const float* __restrict__ rgb) {
    int i = blockIdx.x * blockDim.x + threadIdx.x;     // float4 index
    const int n4 = B_IMG * HW / 4;
    if (i >= n4) return;
    const int hw4 = HW / 4;
    int b  = i / hw4;
    int p4 = i - b * hw4;
    const float4* base = reinterpret_cast<const float4*>(rgb + (size_t)b * 3 * HW) + p4;
    float4 r = base[0];
    float4 g = base[hw4];
    float4 bl = base[2 * hw4];
    float4 y;
    const float k = 1.0f / 3.0f;
    y.x = (r.x + g.x + bl.x) * k;
    y.y = (r.y + g.y + bl.y) * k;
    y.z = (r.z + g.z + bl.z) * k;
    y.w = (r.w + g.w + bl.w) * k;
    reinterpret_cast<float4*>(g_y)[i] = y;
}

// ---------------------------------------------------------------------------
// Kernel 2: tiled NLM. 32x32 tile per block, 512 threads, 2 output px/thread
// (vertical pair). Circular boundary resolved at smem-load time via & 1023.
// Software-pipelined: ONE __syncthreads per shift, double-buffered sd/shs.
//
// Equivalence: reference computes shifted(p) = src(p - s) (roll) for all
// s in [-5,5]^2 and sums; substituting s' = -s over the same symmetric set
// gives a gather sum_{s'} rgb[p+s'] * w(s'), where w comes from the 5x5
// circular box sum of (y(q) - y(q+s'))^2 around p. Stages 1-3 compute that.
// ---------------------------------------------------------------------------
__global__ __launch_bounds__(NT, 2)
void nlm_kernel(const float* __restrict__ rgb, float* __restrict__ out) {
    extern __shared__ float smem[];
    float* const sy   = smem + SY_OFF;
    float* const sdb0 = smem + SD_OFF;
    float* const sdb1 = sdb0 + DH * DS;
    float* const shb0 = smem + SHS_OFF;
    float* const shb1 = shb0 + DH * TILE;
    float* const sr0  = smem + SR_OFF;
    float* const sr1  = sr0 + RH * RH;
    float* const sr2  = sr1 + RH * RH;

    const int tid  = threadIdx.x;
    const int lane = tid & 31;         // output x
    const int wrp  = tid >> 5;         // 0..15 -> output rows 2w, 2w+1
    const int x0   = blockIdx.x * TILE;
    const int y0   = blockIdx.y * TILE;
    const int b    = blockIdx.z;

    // ---- load luminance halo (wrapped) ----
    const float* yb = g_y + (size_t)b * HW;
    for (int i = tid; i < YH * YH; i += NT) {
        int r = i / YH, c = i - r * YH;
        int gy = (y0 + r - YHALO) & (H_IMG - 1);
        int gx = (x0 + c - YHALO) & (W_IMG - 1);
        sy[r * YS + c] = yb[gy * W_IMG + gx];
    }
    // ---- load rgb halo (wrapped) ----
    const float* rgbb = rgb + (size_t)b * 3 * HW;
    for (int i = tid; i < RH * RH; i += NT) {
        int r = i / RH, c = i - r * RH;
        int gy = (y0 + r - RHALO) & (H_IMG - 1);
        int gx = (x0 + c - RHALO) & (W_IMG - 1);
        int o  = gy * W_IMG + gx;
        sr0[i] = rgbb[o];
        sr1[i] = rgbb[o + HW];
        sr2[i] = rgbb[o + 2 * HW];
    }

    // ---- hoisted per-thread index precompute (invariant over shifts) ----
    // Stage 1: 36*36 = 1296 points in up to 3 strided passes.
    int r1a = tid / DH,           c1a = tid - r1a * DH;
    int i1b = tid + NT;   int r1b = i1b / DH, c1b = i1b - r1b * DH;
    int i1c = tid + 2*NT; bool act1c = (i1c < DH * DH);
    int r1c = i1c / DH,           c1c = i1c - r1c * DH;
    const int ai_a = (r1a + 5) * YS + (c1a + 5), di_a = r1a * DS + c1a;
    const int ai_b = (r1b + 5) * YS + (c1b + 5), di_b = r1b * DS + c1b;
    const int ai_c = (r1c + 5) * YS + (c1c + 5), di_c = r1c * DS + c1c;

    // Stage 2: 36 rows x 16 pairs = 576 strips; pass a = tid, pass b = tid+512
    // (active only for tid < 64).
    int r2a = tid >> 4,  cp2a = (tid & 15) << 1;
    int i2b = tid + NT;  bool act2b = (i2b < DH * 16);
    int r2b = i2b >> 4,  cp2b = (i2b & 15) << 1;
    const int s2a_in = r2a * DS + cp2a, s2a_out = r2a * TILE + cp2a;
    const int s2b_in = r2b * DS + cp2b, s2b_out = r2b * TILE + cp2b;

    // Stage 3: output rows rr, rr+1 at column lane.
    const int rr = wrp << 1;
    const int shs_base = rr * TILE + lane;
    const int ro_base  = (rr + RHALO) * RH + (lane + RHALO);

    __syncthreads();

    float a0r = 0.f, a0g = 0.f, a0b = 0.f, w0s = 0.f;
    float a1r = 0.f, a1g = 0.f, a1b = 0.f, w1s = 0.f;
    const float inv_h = 1.0f / (1.0f + 1e-6f);

#define STAGE1(SD, BOFF)                                                      \
    {                                                                         \
        float a, bb, df;                                                      \
        a = sy[ai_a]; bb = sy[ai_a + (BOFF)]; df = a - bb; (SD)[di_a] = df * df; \
        a = sy[ai_b]; bb = sy[ai_b + (BOFF)]; df = a - bb; (SD)[di_b] = df * df; \
        if (act1c) {                                                          \
            a = sy[ai_c]; bb = sy[ai_c + (BOFF)]; df = a - bb; (SD)[di_c] = df * df; \
        }                                                                     \
    }

#define STAGE2(SD, SH)                                                        \
    {                                                                         \
        const float2* p = reinterpret_cast<const float2*>((SD) + s2a_in);     \
        float2 p01 = p[0], p23 = p[1], p45 = p[2];                            \
        float s0 = ((p01.x + p01.y) + (p23.x + p23.y)) + p45.x;               \
        float s1 = ((p01.y + p23.x) + (p23.y + p45.x)) + p45.y;               \
        *reinterpret_cast<float2*>((SH) + s2a_out) = make_float2(s0, s1);     \
        if (act2b) {                                                          \
            const float2* pb = reinterpret_cast<const float2*>((SD) + s2b_in);\
            float2 q01 = pb[0], q23 = pb[1], q45 = pb[2];                     \
            float t0 = ((q01.x + q01.y) + (q23.x + q23.y)) + q45.x;           \
            float t1 = ((q01.y + q23.x) + (q23.y + q45.x)) + q45.y;           \
            *reinterpret_cast<float2*>((SH) + s2b_out) = make_float2(t0, t1); \
        }                                                                     \
    }

#define STAGE3(SH, ROFF)                                                      \
    {                                                                         \
        const float* p = (SH) + shs_base;                                     \
        float v0 = p[0],      v1 = p[TILE],   v2 = p[2*TILE];                 \
        float v3 = p[3*TILE], v4 = p[4*TILE], v5 = p[5*TILE];                 \
        float S0 = ((v0 + v1) + (v2 + v3)) + v4;                              \
        float S1 = ((v1 + v2) + (v3 + v4)) + v5;                              \
        float w0 = __expf(-sqrtf(S0) * inv_h);                                \
        float w1 = __expf(-sqrtf(S1) * inv_h);                                \
        int ro0 = ro_base + (ROFF);                                           \
        int ro1 = ro0 + RH;                                                   \
        a0r = fmaf(sr0[ro0], w0, a0r);                                        \
        a0g = fmaf(sr1[ro0], w0, a0g);                                        \
        a0b = fmaf(sr2[ro0], w0, a0b);                                        \
        w0s += w0;                                                            \
        a1r = fmaf(sr0[ro1], w1, a1r);                                        \
        a1g = fmaf(sr1[ro1], w1, a1g);                                        \
        a1b = fmaf(sr2[ro1], w1, a1b);                                        \
        w1s += w1;                                                            \
    }

    // ---- pipelined 121-shift loop: 1 barrier per shift ----
    // Prologue: shift 0 (dy=-5, dx=-5) -> buffers 0
    int prev_roff;
    {
        const int dy = -5, dx = -5;
        STAGE1(sdb0, dy * YS + dx);
        __syncthreads();
        STAGE2(sdb0, shb0);
        prev_roff = dy * RH + dx;
    }

    #pragma unroll 1
    for (int sidx = 1; sidx < 121; ++sidx) {
        const int q  = sidx / 11;
        const int dy = q - 5;
        const int dx = (sidx - q * 11) - 5;
        const int boff = dy * YS + dx;
        float* const sdc = (sidx & 1) ? sdb1 : sdb0;
        float* const shc = (sidx & 1) ? shb1 : shb0;
        float* const shp = (sidx & 1) ? shb0 : shb1;   // previous shift's sums

        STAGE1(sdc, boff);
        __syncthreads();
        // Safe concurrently: STAGE2 writes shc, STAGE3 reads shp (other buffer).
        STAGE2(sdc, shc);
        STAGE3(shp, prev_roff);
        prev_roff = dy * RH + dx;
    }
    // Epilogue: consume shift 120 (120 & 1 == 0 -> shb0)
    __syncthreads();
    STAGE3(shb0, prev_roff);

    const float iw0 = 1.0f / w0s;
    const float iw1 = 1.0f / w1s;
    const size_t o0 = (size_t)b * 3 * HW + (size_t)(y0 + rr) * W_IMG + (x0 + lane);
    const size_t o1 = o0 + W_IMG;
    out[o0]          = a0r * iw0;
    out[o0 + HW]     = a0g * iw0;
    out[o0 + 2*HW]   = a0b * iw0;
    out[o1]          = a1r * iw1;
    out[o1 + HW]     = a1g * iw1;
    out[o1 + 2*HW]   = a1b * iw1;
}

// ---------------------------------------------------------------------------
extern "C" void kernel_launch(void* const* d_in, const int* in_sizes, int n_in,
                              void* d_out, int out_size) {
    const float* rgb = (const float*)d_in[0];
    float* out = (float*)d_out;

    // Function metadata only (no allocation); persists across calls, legal
    // to (re-)issue — not a stream-ordered operation.
    cudaFuncSetAttribute(nlm_kernel,
                         cudaFuncAttributeMaxDynamicSharedMemorySize,
                         SMEM_BYTES);

    int n4 = B_IMG * HW / 4;
    lum_kernel<<<(n4 + 255) / 256, 256>>>(rgb);

    dim3 grid(W_IMG / TILE, H_IMG / TILE, B_IMG);
    nlm_kernel<<<grid, NT, SMEM_BYTES>>>(rgb, out);
}

// round 9
// speedup vs baseline: 1.3618x; 1.3618x over previous
#include <cuda_runtime.h>

// Problem constants
#define B_IMG 8
#define H_IMG 1024
#define W_IMG 1024
#define HW (H_IMG * W_IMG)

#define TILE   32          // output tile 32x32
#define NT     256         // threads per block (8 warps)

// sy: luminance tile + halo 7 each side -> rows 46, cols 46, stored with
// left pad 3 (y at x(rel) stored at col x+10) so strip reads are 16B-aligned.
#define YROWS  46
#define YS     52          // stride (multiple of 4 -> row-aligned float4)
// hs: horizontal 5-sums, 36 rows (d-rows -2..33) x 32 cols, stride 36.
#define HSS    36
// rgb halo 5 each side
#define RH     42

// Scratch luminance plane (32 MiB) — static device array (allowed).
__device__ float g_y[B_IMG * HW];

// ---------------------------------------------------------------------------
// Kernel 1: y = mean(rgb, channel) — float4
// ---------------------------------------------------------------------------
__global__ void lum_kernel(const float* __restrict__ rgb) {
    int i = blockIdx.x * blockDim.x + threadIdx.x;
    const int n4 = B_IMG * HW / 4;
    if (i >= n4) return;
    const int hw4 = HW / 4;
    int b  = i / hw4;
    int p4 = i - b * hw4;
    const float4* base = reinterpret_cast<const float4*>(rgb + (size_t)b * 3 * HW) + p4;
    float4 r = base[0];
    float4 g = base[hw4];
    float4 bl = base[2 * hw4];
    float4 y;
    const float k = 1.0f / 3.0f;
    y.x = (r.x + g.x + bl.x) * k;
    y.y = (r.y + g.y + bl.y) * k;
    y.z = (r.z + g.z + bl.z) * k;
    y.w = (r.w + g.w + bl.w) * k;
    reinterpret_cast<float4*>(g_y)[i] = y;
}

// Fused stage1+2: 12 shifted y values (v), 12 invariant y values (u) ->
// 12 squared diffs -> 8 horizontal 5-sums -> 2 STS.128.
// v pointer has a compile-time offset per call site (switch on dx&3), so all
// indices are static and everything stays in registers.
__device__ __forceinline__ void fuse12(const float* u, const float* v, float* hrow) {
    float d[12];
#pragma unroll
    for (int k = 0; k < 12; ++k) {
        float df = u[k] - v[k];
        d[k] = df * df;
    }
    float o[8];
#pragma unroll
    for (int k = 0; k < 8; ++k)
        o[k] = ((d[k] + d[k + 1]) + (d[k + 2] + d[k + 3])) + d[k + 4];
    *reinterpret_cast<float4*>(hrow)     = make_float4(o[0], o[1], o[2], o[3]);
    *reinterpret_cast<float4*>(hrow + 4) = make_float4(o[4], o[5], o[6], o[7]);
}

// ---------------------------------------------------------------------------
// Kernel 2: tiled NLM. 32x32 tile, 256 threads, 4 px/thread (2x2) in stage3.
// Circular boundary resolved at smem-load time via & 1023.
//
// Equivalence with reference: reference accumulates roll(rgb,s)(p) * w where
// w = exp(-sqrt(boxsum((y - roll(y,s))^2))(p)). roll(f,s)(q) = f(q-s), so the
// integrand is (y(q)-y(q-s))^2 and the rgb term is rgb(p-s). Substituting
// s' = -s over the same symmetric shift set gives exactly the gather we
// compute: d(q) = (y(q)-y(q+s'))^2 box-summed at p, acc += rgb(p+s')*w.
// ---------------------------------------------------------------------------
__global__ __launch_bounds__(NT, 3)
void nlm_kernel(const float* __restrict__ rgb, float* __restrict__ out) {
    __shared__ __align__(16) float sy[YROWS * YS];        // 2392 floats
    __shared__ __align__(16) float hsb[2][HSS * 36];      // 2 x 1296
    __shared__ float srg[2 * RH * RH];                    // R,G interleaved
    __shared__ float sb[RH * RH];                         // B

    const int tid = threadIdx.x;
    const int x0  = blockIdx.x * TILE;
    const int y0  = blockIdx.y * TILE;
    const int b   = blockIdx.z;

    // ---- load luminance halo (wrapped): rows/cols -7..38 ----
    const float* yb = g_y + (size_t)b * HW;
    for (int i = tid; i < YROWS * 46; i += NT) {
        int r = i / 46, c = i - r * 46;
        int gy = (y0 + r - 7) & (H_IMG - 1);
        int gx = (x0 + c - 7) & (W_IMG - 1);
        sy[r * YS + c + 3] = yb[gy * W_IMG + gx];
    }
    // ---- load rgb halo (wrapped): -5..36 ----
    const float* rgbb = rgb + (size_t)b * 3 * HW;
    for (int i = tid; i < RH * RH; i += NT) {
        int r = i / RH, c = i - r * RH;
        int gy = (y0 + r - 5) & (H_IMG - 1);
        int gx = (x0 + c - 5) & (W_IMG - 1);
        int o  = gy * W_IMG + gx;
        srg[2 * i]     = rgbb[o];
        srg[2 * i + 1] = rgbb[o + HW];
        sb[i]          = rgbb[o + 2 * HW];
    }
    __syncthreads();

    // ---- fused-stage setup (threads 0..143): strip of 8 hs outputs ----
    const bool fact = (tid < 144);
    const int  fh   = tid >> 2;            // hs row 0..35 (d-row fh-2)
    const int  fxs  = (tid & 3) << 3;      // 0,8,16,24
    // Invariant operand: y(d-row fh-2, cols fxs-2..fxs+9) — load ONCE.
    // sy col index of tile-x X is X+10; d-row rd maps to sy row rd+7 = fh+5.
    float uu[12];
    if (fact) {
        const float* urow = sy + (fh + 5) * YS + fxs + 8;   // 16B aligned
        *reinterpret_cast<float4*>(uu)     = *reinterpret_cast<const float4*>(urow);
        *reinterpret_cast<float4*>(uu + 4) = *reinterpret_cast<const float4*>(urow + 4);
        *reinterpret_cast<float4*>(uu + 8) = *reinterpret_cast<const float4*>(urow + 8);
    }

    // ---- stage3 setup: 2x2 output pixels per thread ----
    const int cp = (tid & 15) << 1;        // cols cp, cp+1
    const int rp = (tid >> 4) << 1;        // rows rp, rp+1
    const int s3h    = rp * HSS + cp;
    const int robase = (rp + 5) * RH + (cp + 5);

    float aR00 = 0.f, aG00 = 0.f, aB00 = 0.f, w00s = 0.f;
    float aR01 = 0.f, aG01 = 0.f, aB01 = 0.f, w01s = 0.f;
    float aR10 = 0.f, aG10 = 0.f, aB10 = 0.f, w10s = 0.f;
    float aR11 = 0.f, aG11 = 0.f, aB11 = 0.f, w11s = 0.f;
    const float inv_h = 1.0f / (1.0f + 1e-6f);

    #pragma unroll 1
    for (int sidx = 0; sidx < 121; ++sidx) {
        const int q  = sidx / 11;
        const int dy = q - 5;
        const int dx = (sidx - q * 11) - 5;
        float* const hsc = hsb[sidx & 1];

        // ---- fused stage1+2 ----
        if (fact) {
            const int m = dx & 3;                       // uniform across block
            // aligned base: (dx - m) is a multiple of 4
            const float* srow = sy + (fh + 5 + dy) * YS + fxs + 8 + (dx - m);
            float vv[16];
            *reinterpret_cast<float4*>(vv)      = *reinterpret_cast<const float4*>(srow);
            *reinterpret_cast<float4*>(vv + 4)  = *reinterpret_cast<const float4*>(srow + 4);
            *reinterpret_cast<float4*>(vv + 8)  = *reinterpret_cast<const float4*>(srow + 8);
            *reinterpret_cast<float4*>(vv + 12) = *reinterpret_cast<const float4*>(srow + 12);
            float* hrow = hsc + fh * HSS + fxs;
            switch (m) {                                // uniform branch
                case 0:  fuse12(uu, vv + 0, hrow); break;
                case 1:  fuse12(uu, vv + 1, hrow); break;
                case 2:  fuse12(uu, vv + 2, hrow); break;
                default: fuse12(uu, vv + 3, hrow); break;
            }
        }
        __syncthreads();
        // Double buffer makes this single barrier sufficient: stage3(i) reads
        // hsb[i&1]; the next write to that buffer is fused(i+2), which every
        // thread reaches only after sync(i+1), which follows all stage3(i).

        // ---- stage3: vertical 5-sums, weights, accumulate (all 256) ----
        {
            const float* p = hsc + s3h;
            float2 v0 = *reinterpret_cast<const float2*>(p);
            float2 v1 = *reinterpret_cast<const float2*>(p + HSS);
            float2 v2 = *reinterpret_cast<const float2*>(p + 2 * HSS);
            float2 v3 = *reinterpret_cast<const float2*>(p + 3 * HSS);
            float2 v4 = *reinterpret_cast<const float2*>(p + 4 * HSS);
            float2 v5 = *reinterpret_cast<const float2*>(p + 5 * HSS);
            float t1x = v1.x + v2.x, t1y = v1.y + v2.y;
            float t2x = v3.x + v4.x, t2y = v3.y + v4.y;
            float S0x = (v0.x + t1x) + t2x;      // px (rp,   cp)
            float S0y = (v0.y + t1y) + t2y;      // px (rp,   cp+1)
            float S1x = (t1x + t2x) + v5.x;      // px (rp+1, cp)
            float S1y = (t1y + t2y) + v5.y;      // px (rp+1, cp+1)
            float w00 = __expf(-sqrtf(S0x) * inv_h);
            float w01 = __expf(-sqrtf(S0y) * inv_h);
            float w10 = __expf(-sqrtf(S1x) * inv_h);
            float w11 = __expf(-sqrtf(S1y) * inv_h);

            int ro00 = robase + dy * RH + dx;
            int ro10 = ro00 + RH;
            float2 g00 = *reinterpret_cast<const float2*>(srg + 2 * ro00);
            float2 g01 = *reinterpret_cast<const float2*>(srg + 2 * (ro00 + 1));
            float2 g10 = *reinterpret_cast<const float2*>(srg + 2 * ro10);
            float2 g11 = *reinterpret_cast<const float2*>(srg + 2 * (ro10 + 1));
            float b00 = sb[ro00], b01 = sb[ro00 + 1];
            float b10 = sb[ro10], b11 = sb[ro10 + 1];

            aR00 = fmaf(g00.x, w00, aR00); aG00 = fmaf(g00.y, w00, aG00);
            aB00 = fmaf(b00,   w00, aB00); w00s += w00;
            aR01 = fmaf(g01.x, w01, aR01); aG01 = fmaf(g01.y, w01, aG01);
            aB01 = fmaf(b01,   w01, aB01); w01s += w01;
            aR10 = fmaf(g10.x, w10, aR10); aG10 = fmaf(g10.y, w10, aG10);
            aB10 = fmaf(b10,   w10, aB10); w10s += w10;
            aR11 = fmaf(g11.x, w11, aR11); aG11 = fmaf(g11.y, w11, aG11);
            aB11 = fmaf(b11,   w11, aB11); w11s += w11;
        }
    }

    // ---- normalize + store 4 pixels ----
    const float i00 = 1.0f / w00s, i01 = 1.0f / w01s;
    const float i10 = 1.0f / w10s, i11 = 1.0f / w11s;
    const size_t base0 = (size_t)b * 3 * HW + (size_t)(y0 + rp) * W_IMG + (x0 + cp);
    const size_t base1 = base0 + W_IMG;
    out[base0]              = aR00 * i00;
    out[base0 + HW]         = aG00 * i00;
    out[base0 + 2 * HW]     = aB00 * i00;
    out[base0 + 1]          = aR01 * i01;
    out[base0 + 1 + HW]     = aG01 * i01;
    out[base0 + 1 + 2 * HW] = aB01 * i01;
    out[base1]              = aR10 * i10;
    out[base1 + HW]         = aG10 * i10;
    out[base1 + 2 * HW]     = aB10 * i10;
    out[base1 + 1]          = aR11 * i11;
    out[base1 + 1 + HW]     = aG11 * i11;
    out[base1 + 1 + 2 * HW] = aB11 * i11;
}

// ---------------------------------------------------------------------------
extern "C" void kernel_launch(void* const* d_in, const int* in_sizes, int n_in,
                              void* d_out, int out_size) {
    const float* rgb = (const float*)d_in[0];
    float* out = (float*)d_out;

    int n4 = B_IMG * HW / 4;
    lum_kernel<<<(n4 + 255) / 256, 256>>>(rgb);

    dim3 grid(W_IMG / TILE, H_IMG / TILE, B_IMG);
    nlm_kernel<<<grid, NT>>>(rgb, out);
}

// round 10
// speedup vs baseline: 1.4093x; 1.0349x over previous
#include <cuda_runtime.h>

// Problem constants
#define B_IMG 8
#define H_IMG 1024
#define W_IMG 1024
#define HW (H_IMG * W_IMG)

#define TILE   32          // output tile 32x32
#define NT     256         // threads per block (8 warps)

// sy: luminance tile + halo 7 each side -> rows 46, cols 46, stored with
// left pad 3 (y at x(rel) stored at col x+10) so strip reads are 16B-aligned.
#define YROWS  46
#define YS     52          // stride (multiple of 4 -> row-aligned float4)
// hs: horizontal 5-sums, 36 rows (d-rows -2..33) x 32 cols, stride 36.
#define HSS    36
// rgb halo 5 each side
#define RH     42

// Scratch luminance plane (32 MiB) — static device array (allowed).
__device__ float g_y[B_IMG * HW];

// ---------------------------------------------------------------------------
// Kernel 1: y = mean(rgb, channel) — float4
// ---------------------------------------------------------------------------
__global__ void lum_kernel(const float* __restrict__ rgb) {
    int i = blockIdx.x * blockDim.x + threadIdx.x;
    const int n4 = B_IMG * HW / 4;
    if (i >= n4) return;
    const int hw4 = HW / 4;
    int b  = i / hw4;
    int p4 = i - b * hw4;
    const float4* base = reinterpret_cast<const float4*>(rgb + (size_t)b * 3 * HW) + p4;
    float4 r = base[0];
    float4 g = base[hw4];
    float4 bl = base[2 * hw4];
    float4 y;
    const float k = 1.0f / 3.0f;
    y.x = (r.x + g.x + bl.x) * k;
    y.y = (r.y + g.y + bl.y) * k;
    y.z = (r.z + g.z + bl.z) * k;
    y.w = (r.w + g.w + bl.w) * k;
    reinterpret_cast<float4*>(g_y)[i] = y;
}

// Fused stage1+2: 12 shifted y values (v), 12 invariant y values (u) ->
// 12 squared diffs -> 8 horizontal 5-sums -> 2 STS.128.
__device__ __forceinline__ void fuse12(const float* u, const float* v, float* hrow) {
    float d[12];
#pragma unroll
    for (int k = 0; k < 12; ++k) {
        float df = u[k] - v[k];
        d[k] = df * df;
    }
    float o[8];
#pragma unroll
    for (int k = 0; k < 8; ++k)
        o[k] = ((d[k] + d[k + 1]) + (d[k + 2] + d[k + 3])) + d[k + 4];
    *reinterpret_cast<float4*>(hrow)     = make_float4(o[0], o[1], o[2], o[3]);
    *reinterpret_cast<float4*>(hrow + 4) = make_float4(o[4], o[5], o[6], o[7]);
}

// ---------------------------------------------------------------------------
// Kernel 2: tiled NLM. 32x32 tile, 256 threads, 4 px/thread (2x2) in stage3.
// Circular boundary resolved at smem-load time via & 1023.
//
// Equivalence with reference: reference accumulates roll(rgb,s)(p) * w where
// w = exp(-sqrt(boxsum((y - roll(y,s))^2))(p)). roll(f,s)(q) = f(q-s), so the
// integrand is (y(q)-y(q-s))^2 and the rgb term is rgb(p-s). Substituting
// s' = -s over the same symmetric shift set gives exactly the gather we
// compute: d(q) = (y(q)-y(q+s'))^2 box-summed at p, acc += rgb(p+s')*w.
// ---------------------------------------------------------------------------
__global__ __launch_bounds__(NT, 4)    // force <=64 regs -> 4 blocks/SM
void nlm_kernel(const float* __restrict__ rgb, float* __restrict__ out) {
    __shared__ __align__(16) float sy[YROWS * YS];        // 2392 floats
    __shared__ __align__(16) float hsb[2][HSS * 36];      // 2 x 1296
    __shared__ float srg[2 * RH * RH];                    // R,G interleaved
    __shared__ float sb[RH * RH];                         // B

    const int tid = threadIdx.x;
    const int x0  = blockIdx.x * TILE;
    const int y0  = blockIdx.y * TILE;
    const int b   = blockIdx.z;

    // ---- load luminance halo (wrapped): rows/cols -7..38 ----
    const float* yb = g_y + (size_t)b * HW;
    for (int i = tid; i < YROWS * 46; i += NT) {
        int r = i / 46, c = i - r * 46;
        int gy = (y0 + r - 7) & (H_IMG - 1);
        int gx = (x0 + c - 7) & (W_IMG - 1);
        sy[r * YS + c + 3] = yb[gy * W_IMG + gx];
    }
    // ---- load rgb halo (wrapped): -5..36 ----
    const float* rgbb = rgb + (size_t)b * 3 * HW;
    for (int i = tid; i < RH * RH; i += NT) {
        int r = i / RH, c = i - r * RH;
        int gy = (y0 + r - 5) & (H_IMG - 1);
        int gx = (x0 + c - 5) & (W_IMG - 1);
        int o  = gy * W_IMG + gx;
        srg[2 * i]     = rgbb[o];
        srg[2 * i + 1] = rgbb[o + HW];
        sb[i]          = rgbb[o + 2 * HW];
    }
    __syncthreads();

    // ---- fused-stage setup (threads 0..143): strip of 8 hs outputs ----
    const bool fact = (tid < 144);
    const int  fh   = tid >> 2;            // hs row 0..35 (d-row fh-2)
    const int  fxs  = (tid & 3) << 3;      // 0,8,16,24
    // Invariant operand: y(d-row fh-2, cols fxs-2..fxs+9) — load ONCE.
    float uu[12];
    if (fact) {
        const float* urow = sy + (fh + 5) * YS + fxs + 8;   // 16B aligned
        *reinterpret_cast<float4*>(uu)     = *reinterpret_cast<const float4*>(urow);
        *reinterpret_cast<float4*>(uu + 4) = *reinterpret_cast<const float4*>(urow + 4);
        *reinterpret_cast<float4*>(uu + 8) = *reinterpret_cast<const float4*>(urow + 8);
    }

    // ---- stage3 setup: 2x2 output pixels per thread ----
    const int cp = (tid & 15) << 1;        // cols cp, cp+1
    const int rp = (tid >> 4) << 1;        // rows rp, rp+1
    const int s3h    = rp * HSS + cp;
    const int robase = (rp + 5) * RH + (cp + 5);

    float aR00 = 0.f, aG00 = 0.f, aB00 = 0.f, w00s = 0.f;
    float aR01 = 0.f, aG01 = 0.f, aB01 = 0.f, w01s = 0.f;
    float aR10 = 0.f, aG10 = 0.f, aB10 = 0.f, w10s = 0.f;
    float aR11 = 0.f, aG11 = 0.f, aB11 = 0.f, w11s = 0.f;
    const float inv_h = 1.0f / (1.0f + 1e-6f);

    int dy = -5, dx = -5;                  // incremental shift counters
    #pragma unroll 1
    for (int sidx = 0; sidx < 121; ++sidx) {
        float* const hsc = hsb[sidx & 1];

        // ---- fused stage1+2 ----
        if (fact) {
            const int m = dx & 3;                       // uniform across block
            // aligned base: (dx - m) is a multiple of 4
            const float* srow = sy + (fh + 5 + dy) * YS + fxs + 8 + (dx - m);
            float vv[16];
            *reinterpret_cast<float4*>(vv)      = *reinterpret_cast<const float4*>(srow);
            *reinterpret_cast<float4*>(vv + 4)  = *reinterpret_cast<const float4*>(srow + 4);
            *reinterpret_cast<float4*>(vv + 8)  = *reinterpret_cast<const float4*>(srow + 8);
            *reinterpret_cast<float4*>(vv + 12) = *reinterpret_cast<const float4*>(srow + 12);
            float* hrow = hsc + fh * HSS + fxs;
            switch (m) {                                // uniform branch
                case 0:  fuse12(uu, vv + 0, hrow); break;
                case 1:  fuse12(uu, vv + 1, hrow); break;
                case 2:  fuse12(uu, vv + 2, hrow); break;
                default: fuse12(uu, vv + 3, hrow); break;
            }
        }
        __syncthreads();
        // Double buffer makes this single barrier sufficient: stage3(i) reads
        // hsb[i&1]; the next write to that buffer is fused(i+2), which every
        // thread reaches only after sync(i+1), which follows all stage3(i).

        // ---- stage3: vertical 5-sums, weights, accumulate (all 256) ----
        {
            const float* p = hsc + s3h;
            float2 v0 = *reinterpret_cast<const float2*>(p);
            float2 v1 = *reinterpret_cast<const float2*>(p + HSS);
            float2 v2 = *reinterpret_cast<const float2*>(p + 2 * HSS);
            float2 v3 = *reinterpret_cast<const float2*>(p + 3 * HSS);
            float2 v4 = *reinterpret_cast<const float2*>(p + 4 * HSS);
            float2 v5 = *reinterpret_cast<const float2*>(p + 5 * HSS);
            float t1x = v1.x + v2.x, t1y = v1.y + v2.y;
            float t2x = v3.x + v4.x, t2y = v3.y + v4.y;
            float S0x = (v0.x + t1x) + t2x;      // px (rp,   cp)
            float S0y = (v0.y + t1y) + t2y;      // px (rp,   cp+1)
            float S1x = (t1x + t2x) + v5.x;      // px (rp+1, cp)
            float S1y = (t1y + t2y) + v5.y;      // px (rp+1, cp+1)
            float w00 = __expf(-sqrtf(S0x) * inv_h);
            float w01 = __expf(-sqrtf(S0y) * inv_h);
            float w10 = __expf(-sqrtf(S1x) * inv_h);
            float w11 = __expf(-sqrtf(S1y) * inv_h);

            int ro00 = robase + dy * RH + dx;
            int ro10 = ro00 + RH;
            float2 g00 = *reinterpret_cast<const float2*>(srg + 2 * ro00);
            float2 g01 = *reinterpret_cast<const float2*>(srg + 2 * (ro00 + 1));
            float2 g10 = *reinterpret_cast<const float2*>(srg + 2 * ro10);
            float2 g11 = *reinterpret_cast<const float2*>(srg + 2 * (ro10 + 1));
            float b00 = sb[ro00], b01 = sb[ro00 + 1];
            float b10 = sb[ro10], b11 = sb[ro10 + 1];

            aR00 = fmaf(g00.x, w00, aR00); aG00 = fmaf(g00.y, w00, aG00);
            aB00 = fmaf(b00,   w00, aB00); w00s += w00;
            aR01 = fmaf(g01.x, w01, aR01); aG01 = fmaf(g01.y, w01, aG01);
            aB01 = fmaf(b01,   w01, aB01); w01s += w01;
            aR10 = fmaf(g10.x, w10, aR10); aG10 = fmaf(g10.y, w10, aG10);
            aB10 = fmaf(b10,   w10, aB10); w10s += w10;
            aR11 = fmaf(g11.x, w11, aR11); aG11 = fmaf(g11.y, w11, aG11);
            aB11 = fmaf(b11,   w11, aB11); w11s += w11;
        }

        // advance (dy, dx) through the 11x11 window
        if (++dx > 5) { dx = -5; ++dy; }
    }

    // ---- normalize + store 4 pixels ----
    const float i00 = 1.0f / w00s, i01 = 1.0f / w01s;
    const float i10 = 1.0f / w10s, i11 = 1.0f / w11s;
    const size_t base0 = (size_t)b * 3 * HW + (size_t)(y0 + rp) * W_IMG + (x0 + cp);
    const size_t base1 = base0 + W_IMG;
    out[base0]              = aR00 * i00;
    out[base0 + HW]         = aG00 * i00;
    out[base0 + 2 * HW]     = aB00 * i00;
    out[base0 + 1]          = aR01 * i01;
    out[base0 + 1 + HW]     = aG01 * i01;
    out[base0 + 1 + 2 * HW] = aB01 * i01;
    out[base1]              = aR10 * i10;
    out[base1 + HW]         = aG10 * i10;
    out[base1 + 2 * HW]     = aB10 * i10;
    out[base1 + 1]          = aR11 * i11;
    out[base1 + 1 + HW]     = aG11 * i11;
    out[base1 + 1 + 2 * HW] = aB11 * i11;
}

// ---------------------------------------------------------------------------
extern "C" void kernel_launch(void* const* d_in, const int* in_sizes, int n_in,
                              void* d_out, int out_size) {
    const float* rgb = (const float*)d_in[0];
    float* out = (float*)d_out;

    int n4 = B_IMG * HW / 4;
    lum_kernel<<<(n4 + 255) / 256, 256>>>(rgb);

    dim3 grid(W_IMG / TILE, H_IMG / TILE, B_IMG);
    nlm_kernel<<<grid, NT>>>(rgb, out);
}